// round 9
// baseline (speedup 1.0000x reference)
#include <cuda_runtime.h>
#include <math.h>
#include <stdint.h>

#define Bn 65536
#define K1 1664
#define Nn 200000

// ---------- scratch ----------
__device__ __align__(128) int8_t qX1a1[(size_t)Bn*K1];
__device__ __align__(128) int8_t qX1a2[(size_t)Bn*K1];
__device__ __align__(128) int8_t qX1b1[(size_t)Bn*K1];
__device__ __align__(128) int8_t qX1b2[(size_t)Bn*K1];
__device__ __align__(128) float fH1a[(size_t)Bn*512];
__device__ __align__(128) float fH1b[(size_t)Bn*512];
__device__ __align__(128) float fMs[(size_t)Bn*512];
__device__ __align__(128) float fMd[(size_t)Bn*512];
__device__ __align__(128) int8_t qH1a1[(size_t)Bn*512];
__device__ __align__(128) int8_t qH1a2[(size_t)Bn*512];
__device__ __align__(128) int8_t qH1b1[(size_t)Bn*512];
__device__ __align__(128) int8_t qH1b2[(size_t)Bn*512];
__device__ __align__(128) int8_t qMs1[(size_t)Bn*512];
__device__ __align__(128) int8_t qMs2[(size_t)Bn*512];
__device__ __align__(128) int8_t qMd1[(size_t)Bn*512];
__device__ __align__(128) int8_t qMd2[(size_t)Bn*512];
__device__ __align__(128) float fGhs[(size_t)Bn*1536];
__device__ __align__(128) float fGhd[(size_t)Bn*1536];
__device__ __align__(128) float fGis[(size_t)Bn*1536];
__device__ __align__(128) float fGid[(size_t)Bn*1536];
__device__ __align__(128) float fCs[(size_t)Bn*1024];
__device__ __align__(128) float fCd[(size_t)Bn*1024];
__device__ __align__(128) int8_t qCs1[(size_t)Bn*1024];
__device__ __align__(128) int8_t qCs2[(size_t)Bn*1024];
__device__ __align__(128) int8_t qCd1[(size_t)Bn*1024];
__device__ __align__(128) int8_t qCd2[(size_t)Bn*1024];
__device__ float sX1[Bn], sH1a[Bn], sH1b[Bn], sMsv[Bn], sMdv[Bn], sCsv[Bn], sCdv[Bn];
__device__ __align__(128) int8_t qW11[512*K1];
__device__ __align__(128) int8_t qW12[512*K1];
__device__ __align__(128) int8_t qW21[512*512];
__device__ __align__(128) int8_t qW22[512*512];
__device__ __align__(128) int8_t qWih1[1536*512];
__device__ __align__(128) int8_t qWih2[1536*512];
__device__ __align__(128) int8_t qWhh1[1536*512];
__device__ __align__(128) int8_t qWhh2[1536*512];
__device__ __align__(128) int8_t qWo1[512*1024];
__device__ __align__(128) int8_t qWo2[512*1024];
__device__ float sW1[512], sW2[512], sWih[1536], sWhh[1536], sWo[512];

// ---------- asm ----------
__device__ __forceinline__ uint32_t smem_u32(const void* p) {
    uint32_t a;
    asm("{ .reg .u64 t; cvta.to.shared.u64 t, %1; cvt.u32.u64 %0, t; }" : "=r"(a) : "l"(p));
    return a;
}
__device__ __forceinline__ void cp16(uint32_t d, const void* s) {
    asm volatile("cp.async.cg.shared.global [%0], [%1], 16;" :: "r"(d), "l"(s) : "memory");
}
#define CP_COMMIT() asm volatile("cp.async.commit_group;" ::: "memory")
#define CP_WAIT2() asm volatile("cp.async.wait_group 2;" ::: "memory")
#define LDSM4(r, a) \
    asm volatile("ldmatrix.sync.aligned.m8n8.x4.shared.b16 {%0,%1,%2,%3},[%4];" \
        : "=r"((r)[0]), "=r"((r)[1]), "=r"((r)[2]), "=r"((r)[3]) : "r"(a))
#define LDSM4B(r0, r1, a) \
    asm volatile("ldmatrix.sync.aligned.m8n8.x4.shared.b16 {%0,%1,%2,%3},[%4];" \
        : "=r"((r0)[0]), "=r"((r0)[1]), "=r"((r1)[0]), "=r"((r1)[1]) : "r"(a))
#define IMMA(d, a, b) \
    asm volatile("mma.sync.aligned.m16n8k32.row.col.s32.s8.s8.s32 " \
        "{%0,%1,%2,%3},{%4,%5,%6,%7},{%8,%9},{%0,%1,%2,%3};" \
        : "+r"((d)[0]), "+r"((d)[1]), "+r"((d)[2]), "+r"((d)[3]) \
        : "r"((a)[0]), "r"((a)[1]), "r"((a)[2]), "r"((a)[3]), "r"((b)[0]), "r"((b)[1]))

// ---------- int8 2-digit GEMM ----------
// Block 128x128, BK=64 int8, 8 warps (warp 64x32), 4-stage cp.async.
// smem row = 128B: chunks 0-3 digit1 (k0..63), 4-7 digit2; chunk c of row r
// at r*128 + 16*(c^(r&7)).
#define QA 16384
#define QSTG 32768
#define QSMEM (4 * QSTG)

__global__ void __launch_bounds__(256, 1)
qgemm(const int8_t* __restrict__ A1, const int8_t* __restrict__ A2,
      const float* __restrict__ sA, int lda,
      const int8_t* __restrict__ B1, const int8_t* __restrict__ B2,
      const float* __restrict__ sB, int ldb,
      int K, const float* __restrict__ bias, float* __restrict__ C, int ldc, int relu)
{
    extern __shared__ __align__(128) char smx[];
    const uint32_t sbase = smem_u32(smx);
    const int tid = threadIdx.x, wid = tid >> 5, lane = tid & 31;
    const int wr = wid >> 2, wc = wid & 3;
    const size_t rowA = (size_t)blockIdx.y * 128;
    const int colB = blockIdx.x * 128;
    const int lrow = tid >> 1, lh = tid & 1, lkey = lrow & 7;
    const int8_t* pA = (lh ? A2 : A1) + (rowA + lrow) * lda;
    const int8_t* pB = (lh ? B2 : B1) + ((size_t)colB + lrow) * ldb;

    int accH[4][4][4], accL[4][4][4];
#pragma unroll
    for (int i = 0; i < 4; i++)
#pragma unroll
        for (int j = 0; j < 4; j++)
#pragma unroll
            for (int k = 0; k < 4; k++) { accH[i][j][k] = 0; accL[i][j][k] = 0; }

    const int nk = K >> 6;
    auto load_stage = [&](int kt, int s) {
        const int kc = kt << 6;
        uint32_t dA = sbase + s * QSTG + lrow * 128;
        uint32_t dB = dA + QA;
#pragma unroll
        for (int c = 0; c < 4; c++) {
            cp16(dA + 16 * ((c + 4 * lh) ^ lkey), pA + kc + c * 16);
            cp16(dB + 16 * ((c + 4 * lh) ^ lkey), pB + kc + c * 16);
        }
        CP_COMMIT();
    };
    load_stage(0, 0); load_stage(1, 1); load_stage(2, 2);

    const int g = lane >> 3, r8 = lane & 7;
    const uint32_t aRowOff = (uint32_t)((wr * 64 + (g & 1) * 8 + r8) * 128);
    const uint32_t bRowOff = (uint32_t)((wc * 32 + (g >> 1) * 8 + r8) * 128) + QA;
    const int aCk = g >> 1, bCk = g & 1;

    int s_cur = 0, s_nxt = 3;
    for (int kt = 0; kt < nk; ++kt) {
        CP_WAIT2();
        __syncthreads();
        const uint32_t st = sbase + s_cur * QSTG;
#pragma unroll
        for (int ks = 0; ks < 2; ks++) {
            uint32_t a1[4][4], a2[4][4], b1[4][2], b2[4][2];
            const uint32_t ach = (uint32_t)(16 * ((2 * ks + aCk) ^ r8));
            const uint32_t bch = (uint32_t)(16 * ((2 * ks + bCk) ^ r8));
#pragma unroll
            for (int mt = 0; mt < 4; mt++) {
                uint32_t ad = st + aRowOff + (uint32_t)(mt * 2048);
                LDSM4(a1[mt], ad + ach);
                LDSM4(a2[mt], ad + (ach ^ 64));
            }
#pragma unroll
            for (int np = 0; np < 2; np++) {
                uint32_t bd = st + bRowOff + (uint32_t)(np * 2048);
                LDSM4B(b1[2 * np], b1[2 * np + 1], bd + bch);
                LDSM4B(b2[2 * np], b2[2 * np + 1], bd + (bch ^ 64));
            }
#pragma unroll
            for (int mt = 0; mt < 4; mt++)
#pragma unroll
                for (int nt = 0; nt < 4; nt++) {
                    IMMA(accH[mt][nt], a1[mt], b1[nt]);
                    IMMA(accL[mt][nt], a1[mt], b2[nt]);
                    IMMA(accL[mt][nt], a2[mt], b1[nt]);
                }
        }
        if (kt + 3 < nk) load_stage(kt + 3, s_nxt);
        else CP_COMMIT();
        if (++s_cur == 4) s_cur = 0;
        if (++s_nxt == 4) s_nxt = 0;
    }

    const float iv = 0.0078125f;
#pragma unroll
    for (int mt = 0; mt < 4; mt++) {
        size_t r0 = rowA + wr * 64 + mt * 16 + (lane >> 2);
        float sa0 = sA[r0], sa1 = sA[r0 + 8];
#pragma unroll
        for (int nt = 0; nt < 4; nt++) {
            int col = colB + wc * 32 + nt * 8 + (lane & 3) * 2;
            float sb0 = sB[col], sb1 = sB[col + 1];
            float v0 = sa0 * sb0 * ((float)accH[mt][nt][0] + (float)accL[mt][nt][0] * iv) + bias[col];
            float v1 = sa0 * sb1 * ((float)accH[mt][nt][1] + (float)accL[mt][nt][1] * iv) + bias[col + 1];
            float v2 = sa1 * sb0 * ((float)accH[mt][nt][2] + (float)accL[mt][nt][2] * iv) + bias[col];
            float v3 = sa1 * sb1 * ((float)accH[mt][nt][3] + (float)accL[mt][nt][3] * iv) + bias[col + 1];
            if (relu) {
                v0 = fmaxf(v0, 0.f); v1 = fmaxf(v1, 0.f);
                v2 = fmaxf(v2, 0.f); v3 = fmaxf(v3, 0.f);
            }
            *(float2*)(C + r0 * ldc + col) = make_float2(v0, v1);
            *(float2*)(C + (r0 + 8) * ldc + col) = make_float2(v2, v3);
        }
    }
}

// ---------- quant helpers ----------
__device__ __forceinline__ float blkmax(float v, float* sm) {
#pragma unroll
    for (int o = 16; o; o >>= 1) v = fmaxf(v, __shfl_xor_sync(~0u, v, o));
    int lane = threadIdx.x & 31, wid = threadIdx.x >> 5, nw = blockDim.x >> 5;
    if (lane == 0) sm[wid] = v;
    __syncthreads();
    float r = sm[0];
    for (int i = 1; i < nw; i++) r = fmaxf(r, sm[i]);
    __syncthreads();
    return r;
}
__device__ __forceinline__ void qst2(int8_t* p1, int8_t* p2, size_t o, float2 v, float inv) {
    float xa = v.x * inv, f1 = rintf(xa);
    float xb = v.y * inv, g1 = rintf(xb);
    *(char2*)(p1 + o) = make_char2((char)(int)f1, (char)(int)g1);
    *(char2*)(p2 + o) = make_char2((char)(int)rintf((xa - f1) * 128.f),
                                   (char)(int)rintf((xb - g1) * 128.f));
}

// one block per row; works for weights (256 thr) and activations
__global__ void quantk(const float* __restrict__ X, int cols,
                       int8_t* __restrict__ q1, int8_t* __restrict__ q2,
                       float* __restrict__ s) {
    __shared__ float sm[8];
    int row = blockIdx.x, t = threadIdx.x, nt = blockDim.x;
    const float* xr = X + (size_t)row * cols;
    float m = 0.f;
    for (int i = t; i < cols / 2; i += nt) {
        float2 v = *(const float2*)(xr + 2 * i);
        m = fmaxf(m, fmaxf(fabsf(v.x), fabsf(v.y)));
    }
    m = fmaxf(blkmax(m, sm), 1e-20f);
    float inv = 127.0f / m;
    if (t == 0) s[row] = m / 127.0f;
    int8_t* q1r = q1 + (size_t)row * cols;
    int8_t* q2r = q2 + (size_t)row * cols;
    for (int i = t; i < cols / 2; i += nt) {
        float2 v = *(const float2*)(xr + 2 * i);
        qst2(q1r, q2r, 2 * i, v, inv);
    }
}

// gather + time-enc + quantize X1a=[s,d,e,t], X1b=[d,s,e,t] with one row scale
__global__ void gather_pack_q(const float* __restrict__ mem, const float* __restrict__ edge,
                              const float* __restrict__ ts, const float* __restrict__ tw,
                              const float* __restrict__ tb,
                              const int* __restrict__ sid, const int* __restrict__ did) {
    __shared__ float sm[8];
    int row = blockIdx.x, t = threadIdx.x;   // 256
    int si = sid[row], di = did[row];
    float2 s2 = *(const float2*)(mem + (size_t)si * 512 + 2 * t);
    float2 d2 = *(const float2*)(mem + (size_t)di * 512 + 2 * t);
    float2 e2 = *(const float2*)(edge + (size_t)row * 512 + 2 * t);
    float2 tm2 = make_float2(0.f, 0.f);
    if (t < 64) {
        float tt = ts[row];
        tm2.x = cosf(tt * tw[2 * t] + tb[2 * t]);
        tm2.y = cosf(tt * tw[2 * t + 1] + tb[2 * t + 1]);
    }
    float m = fmaxf(fmaxf(fabsf(s2.x), fabsf(s2.y)), fmaxf(fabsf(d2.x), fabsf(d2.y)));
    m = fmaxf(m, fmaxf(fabsf(e2.x), fabsf(e2.y)));
    m = fmaxf(m, fmaxf(fabsf(tm2.x), fabsf(tm2.y)));
    m = fmaxf(blkmax(m, sm), 1e-20f);
    float inv = 127.0f / m;
    if (t == 0) sX1[row] = m / 127.0f;
    size_t ra = (size_t)row * K1;
    qst2(qX1a1, qX1a2, ra + 2 * t, s2, inv);
    qst2(qX1b1, qX1b2, ra + 512 + 2 * t, s2, inv);
    qst2(qX1a1, qX1a2, ra + 512 + 2 * t, d2, inv);
    qst2(qX1b1, qX1b2, ra + 2 * t, d2, inv);
    qst2(qX1a1, qX1a2, ra + 1024 + 2 * t, e2, inv);
    qst2(qX1b1, qX1b2, ra + 1024 + 2 * t, e2, inv);
    if (t < 64) {
        qst2(qX1a1, qX1a2, ra + 1536 + 2 * t, tm2, inv);
        qst2(qX1b1, qX1b2, ra + 1536 + 2 * t, tm2, inv);
    }
}

__global__ void emb_pack_f(const float* __restrict__ se, const float* __restrict__ de,
                           float* __restrict__ cs, float* __restrict__ cd) {
    int row = blockIdx.x, t = threadIdx.x;
    size_t rb = (size_t)row * 1024 + 512 + 2 * t;
    *(float2*)(cs + rb) = *(const float2*)(se + (size_t)row * 512 + 2 * t);
    *(float2*)(cd + rb) = *(const float2*)(de + (size_t)row * 512 + 2 * t);
}

__device__ __forceinline__ float sigf(float x) { return 1.0f / (1.0f + expf(-x)); }

__global__ void gru_scatter(const float* __restrict__ gi, const float* __restrict__ gh,
                            const float* __restrict__ mem, const int* __restrict__ ids,
                            float* __restrict__ cf, float* __restrict__ out_mem) {
    int row = blockIdx.x, j = threadIdx.x * 4, id = ids[row];
    size_t b3 = (size_t)row * 1536;
    float4 ir = *(const float4*)(gi + b3 + j);
    float4 hr = *(const float4*)(gh + b3 + j);
    float4 iz = *(const float4*)(gi + b3 + 512 + j);
    float4 hz = *(const float4*)(gh + b3 + 512 + j);
    float4 in4 = *(const float4*)(gi + b3 + 1024 + j);
    float4 hn = *(const float4*)(gh + b3 + 1024 + j);
    float4 hv = *(const float4*)(mem + (size_t)id * 512 + j);
    float4 u;
    { float r = sigf(ir.x + hr.x), z = sigf(iz.x + hz.x);
      float n = tanhf(in4.x + r * hn.x); u.x = (1.f - z) * n + z * hv.x; }
    { float r = sigf(ir.y + hr.y), z = sigf(iz.y + hz.y);
      float n = tanhf(in4.y + r * hn.y); u.y = (1.f - z) * n + z * hv.y; }
    { float r = sigf(ir.z + hr.z), z = sigf(iz.z + hz.z);
      float n = tanhf(in4.z + r * hn.z); u.z = (1.f - z) * n + z * hv.z; }
    { float r = sigf(ir.w + hr.w), z = sigf(iz.w + hz.w);
      float n = tanhf(in4.w + r * hn.w); u.w = (1.f - z) * n + z * hv.w; }
    *(float4*)(out_mem + (size_t)id * 512 + j) = u;
    *(float4*)(cf + (size_t)row * 1024 + j) = u;
}

// ---------- launch ----------
extern "C" void kernel_launch(void* const* d_in, const int* in_sizes, int n_in,
                              void* d_out, int out_size) {
    const float* src_emb  = (const float*)d_in[0];
    const float* dst_emb  = (const float*)d_in[1];
    const float* edge     = (const float*)d_in[2];
    const float* ts       = (const float*)d_in[3];
    const float* memory   = (const float*)d_in[4];
    const float* time_w   = (const float*)d_in[5];
    const float* time_b   = (const float*)d_in[6];
    const float* msg_w1   = (const float*)d_in[7];
    const float* msg_b1   = (const float*)d_in[8];
    const float* msg_w2   = (const float*)d_in[9];
    const float* msg_b2   = (const float*)d_in[10];
    const float* gru_w_ih = (const float*)d_in[11];
    const float* gru_w_hh = (const float*)d_in[12];
    const float* gru_b_ih = (const float*)d_in[13];
    const float* gru_b_hh = (const float*)d_in[14];
    const float* out_w    = (const float*)d_in[15];
    const float* out_b    = (const float*)d_in[16];
    const int*   src_ids  = (const int*)d_in[17];
    const int*   dst_ids  = (const int*)d_in[18];

    float* out_y = (float*)d_out;
    float* out_mem = out_y + (size_t)2 * Bn * 512;

    cudaFuncSetAttribute(qgemm, cudaFuncAttributeMaxDynamicSharedMemorySize, QSMEM);

#define SI(p, g) int8_t* p; cudaGetSymbolAddress((void**)&p, g)
#define SF(p, g) float* p; cudaGetSymbolAddress((void**)&p, g)
    SI(pXa1, qX1a1); SI(pXa2, qX1a2); SI(pXb1, qX1b1); SI(pXb2, qX1b2);
    SF(pH1a, fH1a); SF(pH1b, fH1b); SF(pMs, fMs); SF(pMd, fMd);
    SI(pHa1, qH1a1); SI(pHa2, qH1a2); SI(pHb1, qH1b1); SI(pHb2, qH1b2);
    SI(pMs1, qMs1); SI(pMs2, qMs2); SI(pMd1, qMd1); SI(pMd2, qMd2);
    SF(pGhs, fGhs); SF(pGhd, fGhd); SF(pGis, fGis); SF(pGid, fGid);
    SF(pCs, fCs); SF(pCd, fCd);
    SI(pCs1, qCs1); SI(pCs2, qCs2); SI(pCd1, qCd1); SI(pCd2, qCd2);
    SF(psX1, sX1); SF(psHa, sH1a); SF(psHb, sH1b); SF(psMs, sMsv); SF(psMd, sMdv);
    SF(psCs, sCsv); SF(psCd, sCdv);
    SI(pW11, qW11); SI(pW12, qW12); SI(pW21, qW21); SI(pW22, qW22);
    SI(pWih1, qWih1); SI(pWih2, qWih2); SI(pWhh1, qWhh1); SI(pWhh2, qWhh2);
    SI(pWo1, qWo1); SI(pWo2, qWo2);
    SF(psW1, sW1); SF(psW2, sW2); SF(psWih, sWih); SF(psWhh, sWhh); SF(psWo, sWo);
#undef SI
#undef SF

    cudaMemcpyAsync(out_mem, memory, (size_t)Nn * 512 * sizeof(float),
                    cudaMemcpyDeviceToDevice, 0);

    const dim3 g512(4, Bn / 128), g1536(12, Bn / 128);

    gather_pack_q<<<Bn, 256>>>(memory, edge, ts, time_w, time_b, src_ids, dst_ids);
    quantk<<<512, 256>>>(msg_w1, K1, pW11, pW12, psW1);
    quantk<<<1536, 256>>>(gru_w_hh, 512, pWhh1, pWhh2, psWhh);
    // msg layer1 (K=1664, relu)
    qgemm<<<g512, 256, QSMEM>>>(pXa1, pXa2, psX1, K1, pW11, pW12, psW1, K1,
                                K1, msg_b1, pH1a, 512, 1);
    qgemm<<<g512, 256, QSMEM>>>(pXb1, pXb2, psX1, K1, pW11, pW12, psW1, K1,
                                K1, msg_b1, pH1b, 512, 1);
    // GRU gh: src_mem = X1a cols [0,512) (lda=K1), dst_mem = X1b cols [0,512)
    qgemm<<<g1536, 256, QSMEM>>>(pXa1, pXa2, psX1, K1, pWhh1, pWhh2, psWhh, 512,
                                 512, gru_b_hh, pGhs, 1536, 0);
    qgemm<<<g1536, 256, QSMEM>>>(pXb1, pXb2, psX1, K1, pWhh1, pWhh2, psWhh, 512,
                                 512, gru_b_hh, pGhd, 1536, 0);
    // quantize h1
    quantk<<<Bn, 128>>>(pH1a, 512, pHa1, pHa2, psHa);
    quantk<<<Bn, 128>>>(pH1b, 512, pHb1, pHb2, psHb);
    quantk<<<512, 256>>>(msg_w2, 512, pW21, pW22, psW2);
    // msg layer2 (K=512)
    qgemm<<<g512, 256, QSMEM>>>(pHa1, pHa2, psHa, 512, pW21, pW22, psW2, 512,
                                512, msg_b2, pMs, 512, 0);
    qgemm<<<g512, 256, QSMEM>>>(pHb1, pHb2, psHb, 512, pW21, pW22, psW2, 512,
                                512, msg_b2, pMd, 512, 0);
    quantk<<<Bn, 128>>>(pMs, 512, pMs1, pMs2, psMs);
    quantk<<<Bn, 128>>>(pMd, 512, pMd1, pMd2, psMd);
    quantk<<<1536, 256>>>(gru_w_ih, 512, pWih1, pWih2, psWih);
    // GRU gi: gi_src <- dst_to_src msg (Md), gi_dst <- src_to_dst msg (Ms)
    qgemm<<<g1536, 256, QSMEM>>>(pMd1, pMd2, psMd, 512, pWih1, pWih2, psWih, 512,
                                 512, gru_b_ih, pGis, 1536, 0);
    qgemm<<<g1536, 256, QSMEM>>>(pMs1, pMs2, psMs, 512, pWih1, pWih2, psWih, 512,
                                 512, gru_b_ih, pGid, 1536, 0);
    emb_pack_f<<<Bn, 256>>>(src_emb, dst_emb, pCs, pCd);
    gru_scatter<<<Bn, 128>>>(pGis, pGhs, memory, src_ids, pCs, out_mem);
    gru_scatter<<<Bn, 128>>>(pGid, pGhd, memory, dst_ids, pCd, out_mem);
    quantk<<<Bn, 256>>>(pCs, 1024, pCs1, pCs2, psCs);
    quantk<<<Bn, 256>>>(pCd, 1024, pCd1, pCd2, psCd);
    quantk<<<512, 256>>>(out_w, 1024, pWo1, pWo2, psWo);
    // output projection (K=1024)
    qgemm<<<g512, 256, QSMEM>>>(pCs1, pCs2, psCs, 1024, pWo1, pWo2, psWo, 1024,
                                1024, out_b, out_y, 512, 0);
    qgemm<<<g512, 256, QSMEM>>>(pCd1, pCd2, psCd, 1024, pWo1, pWo2, psWo, 1024,
                                1024, out_b, out_y + (size_t)Bn * 512, 512, 0);
}

// round 10
// speedup vs baseline: 4.6429x; 4.6429x over previous
#include <cuda_runtime.h>
#include <cuda_fp16.h>
#include <math.h>
#include <stdint.h>

#define Bn 65536
#define K1 1664
#define Nn 200000

// ---------- scratch ----------
__device__ __align__(128) __half hX1a[(size_t)Bn * K1];
__device__ __align__(128) __half hX1b[(size_t)Bn * K1];
__device__ __align__(128) __half hH1a[(size_t)Bn * 512];
__device__ __align__(128) __half hH1b[(size_t)Bn * 512];
__device__ __align__(128) __half hMs[(size_t)Bn * 512];
__device__ __align__(128) __half hMd[(size_t)Bn * 512];
__device__ __align__(128) float fGhs[(size_t)Bn * 1536];
__device__ __align__(128) float fGhd[(size_t)Bn * 1536];
__device__ __align__(128) float fGis[(size_t)Bn * 1536];
__device__ __align__(128) float fGid[(size_t)Bn * 1536];
__device__ __align__(128) __half hCs[(size_t)Bn * 1024];
__device__ __align__(128) __half hCd[(size_t)Bn * 1024];
__device__ __align__(128) __half hW1[512 * K1];
__device__ __align__(128) __half hW2[512 * 512];
__device__ __align__(128) __half hWih[1536 * 512];
__device__ __align__(128) __half hWhh[1536 * 512];
__device__ __align__(128) __half hWo[512 * 1024];

// ---------- asm ----------
__device__ __forceinline__ uint32_t smem_u32(const void* p) {
    uint32_t a;
    asm("{ .reg .u64 t; cvta.to.shared.u64 t, %1; cvt.u32.u64 %0, t; }" : "=r"(a) : "l"(p));
    return a;
}
__device__ __forceinline__ void cp16(uint32_t d, const void* s) {
    asm volatile("cp.async.cg.shared.global [%0], [%1], 16;" :: "r"(d), "l"(s) : "memory");
}
#define CP_COMMIT() asm volatile("cp.async.commit_group;" ::: "memory")
#define CP_WAIT1() asm volatile("cp.async.wait_group 1;" ::: "memory")
#define LDSM4(r, a) \
    asm volatile("ldmatrix.sync.aligned.m8n8.x4.shared.b16 {%0,%1,%2,%3},[%4];" \
        : "=r"((r)[0]), "=r"((r)[1]), "=r"((r)[2]), "=r"((r)[3]) : "r"(a))
#define LDSM4B(r0, r1, a) \
    asm volatile("ldmatrix.sync.aligned.m8n8.x4.shared.b16 {%0,%1,%2,%3},[%4];" \
        : "=r"((r0)[0]), "=r"((r0)[1]), "=r"((r1)[0]), "=r"((r1)[1]) : "r"(a))
#define MMAH(d, a, b) \
    asm volatile("mma.sync.aligned.m16n8k16.row.col.f32.f16.f16.f32 " \
        "{%0,%1,%2,%3},{%4,%5,%6,%7},{%8,%9},{%0,%1,%2,%3};" \
        : "+f"((d)[0]), "+f"((d)[1]), "+f"((d)[2]), "+f"((d)[3]) \
        : "r"((a)[0]), "r"((a)[1]), "r"((a)[2]), "r"((a)[3]), "r"((b)[0]), "r"((b)[1]))

// ---------- fp16 GEMM: C = A @ B^T + bias ----------
// Block 128x128, BK=64 fp16 (128B rows), 4 warps (64x64 warp tile),
// 3-stage cp.async, XOR swizzle: chunk c of row r at r*128 + 16*(c^(r&7)).
// mode 0: fp32 C; 1: relu -> half H; 2: -> half H
#define A_B 16384
#define STG (2 * A_B)
#define GSMEM (3 * STG)   // 98304

__global__ void __launch_bounds__(128, 2)
hgemm(const __half* __restrict__ A, int lda,
      const __half* __restrict__ B, int ldb, int K,
      const float* __restrict__ bias,
      float* __restrict__ C, int ldc,
      __half* __restrict__ H, int ldo, int mode)
{
    extern __shared__ __align__(128) char smx[];
    const uint32_t sbase = smem_u32(smx);
    const int tid = threadIdx.x, wid = tid >> 5, lane = tid & 31;
    const int wr = wid >> 1, wc = wid & 1;
    const size_t rowA = (size_t)blockIdx.y * 128;
    const int colB = blockIdx.x * 128;
    const __half* pA = A + (rowA + tid) * lda;
    const __half* pB = B + ((size_t)colB + tid) * ldb;
    const int key = tid & 7;

    float acc[4][8][4];
#pragma unroll
    for (int i = 0; i < 4; i++)
#pragma unroll
        for (int j = 0; j < 8; j++) {
            acc[i][j][0] = 0.f; acc[i][j][1] = 0.f;
            acc[i][j][2] = 0.f; acc[i][j][3] = 0.f;
        }

    const int nk = K >> 6;
    auto load_stage = [&](int kt, int s) {
        const int kc = kt << 6;
        uint32_t dA = sbase + s * STG + tid * 128;
#pragma unroll
        for (int c = 0; c < 8; c++) {
            cp16(dA + 16 * (c ^ key), pA + kc + c * 8);
            cp16(dA + A_B + 16 * (c ^ key), pB + kc + c * 8);
        }
        CP_COMMIT();
    };
    load_stage(0, 0);
    load_stage(1, 1);

    const int g = lane >> 3, r8 = lane & 7;
    const uint32_t aRowOff = (uint32_t)((wr * 64 + (g & 1) * 8 + r8) * 128);
    const uint32_t bRowOff = (uint32_t)((wc * 64 + (g >> 1) * 8 + r8) * 128) + A_B;
    const int aCk = g >> 1, bCk = g & 1;

    int s_cur = 0, s_nxt = 2;
    for (int kt = 0; kt < nk; ++kt) {
        CP_WAIT1();
        __syncthreads();
        const uint32_t st = sbase + s_cur * STG;
#pragma unroll
        for (int ks = 0; ks < 4; ks++) {
            uint32_t av[4][4], bv[8][2];
            const uint32_t ach = (uint32_t)(16 * ((2 * ks + aCk) ^ r8));
            const uint32_t bch = (uint32_t)(16 * ((2 * ks + bCk) ^ r8));
#pragma unroll
            for (int mt = 0; mt < 4; mt++)
                LDSM4(av[mt], st + aRowOff + (uint32_t)(mt * 2048) + ach);
#pragma unroll
            for (int np = 0; np < 4; np++)
                LDSM4B(bv[2 * np], bv[2 * np + 1],
                       st + bRowOff + (uint32_t)(np * 2048) + bch);
#pragma unroll
            for (int mt = 0; mt < 4; mt++)
#pragma unroll
                for (int nt = 0; nt < 8; nt++)
                    MMAH(acc[mt][nt], av[mt], bv[nt]);
        }
        if (kt + 2 < nk) load_stage(kt + 2, s_nxt);
        else CP_COMMIT();
        if (++s_cur == 3) s_cur = 0;
        if (++s_nxt == 3) s_nxt = 0;
    }

#pragma unroll
    for (int mt = 0; mt < 4; mt++) {
        size_t r0 = rowA + wr * 64 + mt * 16 + (lane >> 2);
#pragma unroll
        for (int nt = 0; nt < 8; nt++) {
            int col = colB + wc * 64 + nt * 8 + (lane & 3) * 2;
            float b0 = bias[col], b1 = bias[col + 1];
            float v0 = acc[mt][nt][0] + b0, v1 = acc[mt][nt][1] + b1;
            float v2 = acc[mt][nt][2] + b0, v3 = acc[mt][nt][3] + b1;
            if (mode == 0) {
                *(float2*)(C + r0 * ldc + col) = make_float2(v0, v1);
                *(float2*)(C + (r0 + 8) * ldc + col) = make_float2(v2, v3);
            } else {
                if (mode == 1) {
                    v0 = fmaxf(v0, 0.f); v1 = fmaxf(v1, 0.f);
                    v2 = fmaxf(v2, 0.f); v3 = fmaxf(v3, 0.f);
                }
                *(__half2*)(H + r0 * ldo + col) = __floats2half2_rn(v0, v1);
                *(__half2*)(H + (r0 + 8) * ldo + col) = __floats2half2_rn(v2, v3);
            }
        }
    }
}

// ---------- elementwise ----------
__global__ void conv_h(const float* __restrict__ w, __half* __restrict__ h, int n) {
    int i = blockIdx.x * blockDim.x + threadIdx.x;
    if (i < n / 2) {
        float2 v = *(const float2*)(w + 2 * i);
        *(__half2*)(h + 2 * i) = __floats2half2_rn(v.x, v.y);
    }
}

__global__ void gather_pack(const float* __restrict__ mem, const float* __restrict__ edge,
                            const float* __restrict__ ts, const float* __restrict__ tw,
                            const float* __restrict__ tb,
                            const int* __restrict__ sid, const int* __restrict__ did) {
    int row = blockIdx.x, t = threadIdx.x;   // 256
    size_t ra = (size_t)row * K1;
    int si = sid[row], di = did[row];
    float2 s2 = *(const float2*)(mem + (size_t)si * 512 + 2 * t);
    float2 d2 = *(const float2*)(mem + (size_t)di * 512 + 2 * t);
    float2 e2 = *(const float2*)(edge + (size_t)row * 512 + 2 * t);
    __half2 hs = __floats2half2_rn(s2.x, s2.y);
    __half2 hd = __floats2half2_rn(d2.x, d2.y);
    __half2 he = __floats2half2_rn(e2.x, e2.y);
    *(__half2*)(hX1a + ra + 2 * t) = hs;
    *(__half2*)(hX1b + ra + 512 + 2 * t) = hs;
    *(__half2*)(hX1a + ra + 512 + 2 * t) = hd;
    *(__half2*)(hX1b + ra + 2 * t) = hd;
    *(__half2*)(hX1a + ra + 1024 + 2 * t) = he;
    *(__half2*)(hX1b + ra + 1024 + 2 * t) = he;
    if (t < 64) {
        float tt = ts[row];
        float cx = cosf(tt * tw[2 * t] + tb[2 * t]);
        float cy = cosf(tt * tw[2 * t + 1] + tb[2 * t + 1]);
        __half2 hc = __floats2half2_rn(cx, cy);
        *(__half2*)(hX1a + ra + 1536 + 2 * t) = hc;
        *(__half2*)(hX1b + ra + 1536 + 2 * t) = hc;
    }
}

__global__ void emb_pack(const float* __restrict__ se, const float* __restrict__ de) {
    int row = blockIdx.x, t = threadIdx.x;  // 256
    size_t rb = (size_t)row * 1024 + 512 + 2 * t;
    float2 a = *(const float2*)(se + (size_t)row * 512 + 2 * t);
    float2 b = *(const float2*)(de + (size_t)row * 512 + 2 * t);
    *(__half2*)(hCs + rb) = __floats2half2_rn(a.x, a.y);
    *(__half2*)(hCd + rb) = __floats2half2_rn(b.x, b.y);
}

__device__ __forceinline__ float sigf(float x) { return 1.0f / (1.0f + expf(-x)); }

__global__ void gru_scatter(const float* __restrict__ gi, const float* __restrict__ gh,
                            const float* __restrict__ mem, const int* __restrict__ ids,
                            __half* __restrict__ ch, float* __restrict__ out_mem) {
    int row = blockIdx.x, j = threadIdx.x * 4, id = ids[row];
    size_t b3 = (size_t)row * 1536;
    float4 ir = *(const float4*)(gi + b3 + j);
    float4 hr = *(const float4*)(gh + b3 + j);
    float4 iz = *(const float4*)(gi + b3 + 512 + j);
    float4 hz = *(const float4*)(gh + b3 + 512 + j);
    float4 in4 = *(const float4*)(gi + b3 + 1024 + j);
    float4 hn = *(const float4*)(gh + b3 + 1024 + j);
    float4 hv = *(const float4*)(mem + (size_t)id * 512 + j);
    float4 u;
    { float r = sigf(ir.x + hr.x), z = sigf(iz.x + hz.x);
      float n = tanhf(in4.x + r * hn.x); u.x = (1.f - z) * n + z * hv.x; }
    { float r = sigf(ir.y + hr.y), z = sigf(iz.y + hz.y);
      float n = tanhf(in4.y + r * hn.y); u.y = (1.f - z) * n + z * hv.y; }
    { float r = sigf(ir.z + hr.z), z = sigf(iz.z + hz.z);
      float n = tanhf(in4.z + r * hn.z); u.z = (1.f - z) * n + z * hv.z; }
    { float r = sigf(ir.w + hr.w), z = sigf(iz.w + hz.w);
      float n = tanhf(in4.w + r * hn.w); u.w = (1.f - z) * n + z * hv.w; }
    *(float4*)(out_mem + (size_t)id * 512 + j) = u;
    size_t cb = (size_t)row * 1024 + j;
    *(__half2*)(ch + cb) = __floats2half2_rn(u.x, u.y);
    *(__half2*)(ch + cb + 2) = __floats2half2_rn(u.z, u.w);
}

// ---------- launch ----------
extern "C" void kernel_launch(void* const* d_in, const int* in_sizes, int n_in,
                              void* d_out, int out_size) {
    const float* src_emb  = (const float*)d_in[0];
    const float* dst_emb  = (const float*)d_in[1];
    const float* edge     = (const float*)d_in[2];
    const float* ts       = (const float*)d_in[3];
    const float* memory   = (const float*)d_in[4];
    const float* time_w   = (const float*)d_in[5];
    const float* time_b   = (const float*)d_in[6];
    const float* msg_w1   = (const float*)d_in[7];
    const float* msg_b1   = (const float*)d_in[8];
    const float* msg_w2   = (const float*)d_in[9];
    const float* msg_b2   = (const float*)d_in[10];
    const float* gru_w_ih = (const float*)d_in[11];
    const float* gru_w_hh = (const float*)d_in[12];
    const float* gru_b_ih = (const float*)d_in[13];
    const float* gru_b_hh = (const float*)d_in[14];
    const float* out_w    = (const float*)d_in[15];
    const float* out_b    = (const float*)d_in[16];
    const int*   src_ids  = (const int*)d_in[17];
    const int*   dst_ids  = (const int*)d_in[18];

    float* out_y = (float*)d_out;
    float* out_mem = out_y + (size_t)2 * Bn * 512;

    cudaFuncSetAttribute(hgemm, cudaFuncAttributeMaxDynamicSharedMemorySize, GSMEM);

#define SH(p, g) __half* p; cudaGetSymbolAddress((void**)&p, g)
#define SF(p, g) float* p; cudaGetSymbolAddress((void**)&p, g)
    SH(pXa, hX1a); SH(pXb, hX1b); SH(pH1a, hH1a); SH(pH1b, hH1b);
    SH(pMs, hMs); SH(pMd, hMd); SH(pCs, hCs); SH(pCd, hCd);
    SH(pW1, hW1); SH(pW2, hW2); SH(pWih, hWih); SH(pWhh, hWhh); SH(pWo, hWo);
    SF(pGhs, fGhs); SF(pGhd, fGhd); SF(pGis, fGis); SF(pGid, fGid);
#undef SH
#undef SF

    cudaMemcpyAsync(out_mem, memory, (size_t)Nn * 512 * sizeof(float),
                    cudaMemcpyDeviceToDevice, 0);

    const dim3 g512(4, Bn / 128), g1536(12, Bn / 128);
    #define CVT(src, dst, n) conv_h<<<((n) / 2 + 255) / 256, 256>>>(src, dst, n)

    CVT(msg_w1, pW1, 512 * K1);
    gather_pack<<<Bn, 256>>>(memory, edge, ts, time_w, time_b, src_ids, dst_ids);
    CVT(gru_w_hh, pWhh, 1536 * 512);
    // msg layer1 (K=1664) relu -> half
    hgemm<<<g512, 128, GSMEM>>>(pXa, K1, pW1, K1, K1, msg_b1,
                                (float*)0, 0, pH1a, 512, 1);
    hgemm<<<g512, 128, GSMEM>>>(pXb, K1, pW1, K1, K1, msg_b1,
                                (float*)0, 0, pH1b, 512, 1);
    // GRU gh: src_mem = X1a cols[0,512) (lda=K1); dst_mem = X1b cols[0,512)
    hgemm<<<g1536, 128, GSMEM>>>(pXa, K1, pWhh, 512, 512, gru_b_hh,
                                 pGhs, 1536, (__half*)0, 0, 0);
    hgemm<<<g1536, 128, GSMEM>>>(pXb, K1, pWhh, 512, 512, gru_b_hh,
                                 pGhd, 1536, (__half*)0, 0, 0);
    CVT(msg_w2, pW2, 512 * 512);
    // msg layer2 (K=512) -> half
    hgemm<<<g512, 128, GSMEM>>>(pH1a, 512, pW2, 512, 512, msg_b2,
                                (float*)0, 0, pMs, 512, 2);
    hgemm<<<g512, 128, GSMEM>>>(pH1b, 512, pW2, 512, 512, msg_b2,
                                (float*)0, 0, pMd, 512, 2);
    CVT(gru_w_ih, pWih, 1536 * 512);
    // GRU gi: gi_src <- d2s msg (Md), gi_dst <- s2d msg (Ms)
    hgemm<<<g1536, 128, GSMEM>>>(pMd, 512, pWih, 512, 512, gru_b_ih,
                                 pGis, 1536, (__half*)0, 0, 0);
    hgemm<<<g1536, 128, GSMEM>>>(pMs, 512, pWih, 512, 512, gru_b_ih,
                                 pGid, 1536, (__half*)0, 0, 0);
    emb_pack<<<Bn, 256>>>(src_emb, dst_emb);
    gru_scatter<<<Bn, 128>>>(pGis, pGhs, memory, src_ids, pCs, out_mem);
    gru_scatter<<<Bn, 128>>>(pGid, pGhd, memory, dst_ids, pCd, out_mem);
    CVT(out_w, pWo, 512 * 1024);
    // output projection (K=1024)
    hgemm<<<g512, 128, GSMEM>>>(pCs, 1024, pWo, 1024, 1024, out_b,
                                out_y, 512, (__half*)0, 0, 0);
    hgemm<<<g512, 128, GSMEM>>>(pCd, 1024, pWo, 1024, 1024, out_b,
                                out_y + (size_t)Bn * 512, 512, (__half*)0, 0, 0);
}

// round 11
// speedup vs baseline: 4.6524x; 1.0021x over previous
#include <cuda_runtime.h>
#include <cuda_fp16.h>
#include <math.h>
#include <stdint.h>

#define Bn 65536
#define K1 1664
#define Nn 200000

// ---------- scratch ----------
__device__ __align__(128) __half hX1a[(size_t)Bn * K1];
__device__ __align__(128) __half hMem[(size_t)2 * Bn * 512];   // [src_mem; dst_mem]
__device__ __align__(128) __half hH1[(size_t)2 * Bn * 512];    // [H1a; H1b]
__device__ __align__(128) __half hM[(size_t)2 * Bn * 512];     // [Ms; Md]
__device__ __align__(128) float fGh[(size_t)2 * Bn * 1536];    // [gh_s; gh_d]
__device__ __align__(128) float fGi[(size_t)2 * Bn * 1536];    // [gi_d; gi_s] (A=[Ms;Md])
__device__ __align__(128) __half hC[(size_t)2 * Bn * 1024];    // [Cs; Cd]
__device__ __align__(128) __half hW1s[1024 * K1];              // [W1; W1perm]
__device__ __align__(128) __half hW2[512 * 512];
__device__ __align__(128) __half hWih[1536 * 512];
__device__ __align__(128) __half hWhh[1536 * 512];
__device__ __align__(128) __half hWo[512 * 1024];
__device__ float dB1[1024];

// ---------- asm ----------
__device__ __forceinline__ uint32_t smem_u32(const void* p) {
    uint32_t a;
    asm("{ .reg .u64 t; cvta.to.shared.u64 t, %1; cvt.u32.u64 %0, t; }" : "=r"(a) : "l"(p));
    return a;
}
__device__ __forceinline__ void cp16(uint32_t d, const void* s) {
    asm volatile("cp.async.cg.shared.global [%0], [%1], 16;" :: "r"(d), "l"(s) : "memory");
}
#define CP_COMMIT() asm volatile("cp.async.commit_group;" ::: "memory")
#define CP_WAIT1() asm volatile("cp.async.wait_group 1;" ::: "memory")
#define LDSM4(r, a) \
    asm volatile("ldmatrix.sync.aligned.m8n8.x4.shared.b16 {%0,%1,%2,%3},[%4];" \
        : "=r"((r)[0]), "=r"((r)[1]), "=r"((r)[2]), "=r"((r)[3]) : "r"(a))
#define LDSM4B(r0, r1, a) \
    asm volatile("ldmatrix.sync.aligned.m8n8.x4.shared.b16 {%0,%1,%2,%3},[%4];" \
        : "=r"((r0)[0]), "=r"((r0)[1]), "=r"((r1)[0]), "=r"((r1)[1]) : "r"(a))
#define MMAH(d, a, b) \
    asm volatile("mma.sync.aligned.m16n8k16.row.col.f32.f16.f16.f32 " \
        "{%0,%1,%2,%3},{%4,%5,%6,%7},{%8,%9},{%0,%1,%2,%3};" \
        : "+f"((d)[0]), "+f"((d)[1]), "+f"((d)[2]), "+f"((d)[3]) \
        : "r"((a)[0]), "r"((a)[1]), "r"((a)[2]), "r"((a)[3]), "r"((b)[0]), "r"((b)[1]))

// ---------- fp16 GEMM: C = A @ B^T + bias ----------
// Block 128x128, BK=64 fp16 (128B rows), 4 warps (64x64), 3-stage cp.async,
// XOR swizzle: chunk c of row r at r*128 + 16*(c^(r&7)).
// mode 0: fp32 C; 1: relu->half; 2: ->half; 3: relu->half, tiles with
// colB>=512 store to H + Bn*512 at col-512 (row-stacked dual output).
#define A_B 16384
#define STG (2 * A_B)
#define GSMEM (3 * STG)

__global__ void __launch_bounds__(128, 2)
hgemm(const __half* __restrict__ A, int lda,
      const __half* __restrict__ B, int ldb, int K,
      const float* __restrict__ bias,
      float* __restrict__ C, int ldc,
      __half* __restrict__ H, int ldo, int mode)
{
    extern __shared__ __align__(128) char smx[];
    const uint32_t sbase = smem_u32(smx);
    const int tid = threadIdx.x, wid = tid >> 5, lane = tid & 31;
    const int wr = wid >> 1, wc = wid & 1;
    const size_t rowA = (size_t)blockIdx.y * 128;
    const int colB = blockIdx.x * 128;
    const __half* pA = A + (rowA + tid) * lda;
    const __half* pB = B + ((size_t)colB + tid) * ldb;
    const int key = tid & 7;

    float acc[4][8][4];
#pragma unroll
    for (int i = 0; i < 4; i++)
#pragma unroll
        for (int j = 0; j < 8; j++) {
            acc[i][j][0] = 0.f; acc[i][j][1] = 0.f;
            acc[i][j][2] = 0.f; acc[i][j][3] = 0.f;
        }

    const int nk = K >> 6;
    auto load_stage = [&](int kt, int s) {
        const int kc = kt << 6;
        uint32_t dA = sbase + s * STG + tid * 128;
#pragma unroll
        for (int c = 0; c < 8; c++) {
            cp16(dA + 16 * (c ^ key), pA + kc + c * 8);
            cp16(dA + A_B + 16 * (c ^ key), pB + kc + c * 8);
        }
        CP_COMMIT();
    };
    load_stage(0, 0);
    load_stage(1, 1);

    const int g = lane >> 3, r8 = lane & 7;
    const uint32_t aRowOff = (uint32_t)((wr * 64 + (g & 1) * 8 + r8) * 128);
    const uint32_t bRowOff = (uint32_t)((wc * 64 + (g >> 1) * 8 + r8) * 128) + A_B;
    const int aCk = g >> 1, bCk = g & 1;

    int s_cur = 0, s_nxt = 2;
    for (int kt = 0; kt < nk; ++kt) {
        CP_WAIT1();
        __syncthreads();
        const uint32_t st = sbase + s_cur * STG;
#pragma unroll
        for (int ks = 0; ks < 4; ks++) {
            uint32_t av[4][4], bv[8][2];
            const uint32_t ach = (uint32_t)(16 * ((2 * ks + aCk) ^ r8));
            const uint32_t bch = (uint32_t)(16 * ((2 * ks + bCk) ^ r8));
#pragma unroll
            for (int mt = 0; mt < 4; mt++)
                LDSM4(av[mt], st + aRowOff + (uint32_t)(mt * 2048) + ach);
#pragma unroll
            for (int np = 0; np < 4; np++)
                LDSM4B(bv[2 * np], bv[2 * np + 1],
                       st + bRowOff + (uint32_t)(np * 2048) + bch);
#pragma unroll
            for (int mt = 0; mt < 4; mt++)
#pragma unroll
                for (int nt = 0; nt < 8; nt++)
                    MMAH(acc[mt][nt], av[mt], bv[nt]);
        }
        if (kt + 2 < nk) load_stage(kt + 2, s_nxt);
        else CP_COMMIT();
        if (++s_cur == 3) s_cur = 0;
        if (++s_nxt == 3) s_nxt = 0;
    }

    const __half* dummy = 0; (void)dummy;
    __half* Hb = H;
    int cSub = 0;
    if (mode == 3 && colB >= 512) { Hb = H + (size_t)Bn * 512; cSub = 512; }
    const int doRelu = (mode == 1 || mode == 3);

#pragma unroll
    for (int mt = 0; mt < 4; mt++) {
        size_t r0 = rowA + wr * 64 + mt * 16 + (lane >> 2);
#pragma unroll
        for (int nt = 0; nt < 8; nt++) {
            int col = colB + wc * 64 + nt * 8 + (lane & 3) * 2;
            float b0 = bias[col], b1 = bias[col + 1];
            float v0 = acc[mt][nt][0] + b0, v1 = acc[mt][nt][1] + b1;
            float v2 = acc[mt][nt][2] + b0, v3 = acc[mt][nt][3] + b1;
            if (mode == 0) {
                *(float2*)(C + r0 * ldc + col) = make_float2(v0, v1);
                *(float2*)(C + (r0 + 8) * ldc + col) = make_float2(v2, v3);
            } else {
                if (doRelu) {
                    v0 = fmaxf(v0, 0.f); v1 = fmaxf(v1, 0.f);
                    v2 = fmaxf(v2, 0.f); v3 = fmaxf(v3, 0.f);
                }
                int cs = col - cSub;
                *(__half2*)(Hb + r0 * ldo + cs) = __floats2half2_rn(v0, v1);
                *(__half2*)(Hb + (r0 + 8) * ldo + cs) = __floats2half2_rn(v2, v3);
            }
        }
    }
}

// ---------- elementwise ----------
__global__ void conv_h(const float* __restrict__ w, __half* __restrict__ h, int n) {
    int i = blockIdx.x * blockDim.x + threadIdx.x;
    if (i < n / 2) {
        float2 v = *(const float2*)(w + 2 * i);
        *(__half2*)(h + 2 * i) = __floats2half2_rn(v.x, v.y);
    }
}

// build stacked weight [W1; W1 with K-blocks 0/1 swapped]
__global__ void w1_pack(const float* __restrict__ w1) {
    int i = blockIdx.x * blockDim.x + threadIdx.x;   // over 1024*K1
    if (i >= 1024 * K1) return;
    int n = i / K1, k = i % K1;
    int src;
    if (n < 512) src = n * K1 + k;
    else {
        int kk = (k < 512) ? k + 512 : (k < 1024 ? k - 512 : k);
        src = (n - 512) * K1 + kk;
    }
    hW1s[i] = __float2half(w1[src]);
}

__global__ void b1_pack(const float* __restrict__ b) {
    int i = threadIdx.x + blockIdx.x * blockDim.x;
    if (i < 1024) dB1[i] = b[i & 511];
}

__global__ void gather_pack(const float* __restrict__ mem, const float* __restrict__ edge,
                            const float* __restrict__ ts, const float* __restrict__ tw,
                            const float* __restrict__ tb,
                            const int* __restrict__ sid, const int* __restrict__ did) {
    int row = blockIdx.x, t = threadIdx.x;   // 256
    size_t ra = (size_t)row * K1;
    int si = sid[row], di = did[row];
    float2 s2 = *(const float2*)(mem + (size_t)si * 512 + 2 * t);
    float2 d2 = *(const float2*)(mem + (size_t)di * 512 + 2 * t);
    float2 e2 = *(const float2*)(edge + (size_t)row * 512 + 2 * t);
    __half2 hs = __floats2half2_rn(s2.x, s2.y);
    __half2 hd = __floats2half2_rn(d2.x, d2.y);
    __half2 he = __floats2half2_rn(e2.x, e2.y);
    *(__half2*)(hX1a + ra + 2 * t) = hs;
    *(__half2*)(hX1a + ra + 512 + 2 * t) = hd;
    *(__half2*)(hX1a + ra + 1024 + 2 * t) = he;
    *(__half2*)(hMem + (size_t)row * 512 + 2 * t) = hs;
    *(__half2*)(hMem + (size_t)(Bn + row) * 512 + 2 * t) = hd;
    if (t < 64) {
        float tt = ts[row];
        float cx = cosf(tt * tw[2 * t] + tb[2 * t]);
        float cy = cosf(tt * tw[2 * t + 1] + tb[2 * t + 1]);
        *(__half2*)(hX1a + ra + 1536 + 2 * t) = __floats2half2_rn(cx, cy);
    }
}

__global__ void emb_pack(const float* __restrict__ se, const float* __restrict__ de) {
    int row = blockIdx.x, t = threadIdx.x;  // 256
    float2 a = *(const float2*)(se + (size_t)row * 512 + 2 * t);
    float2 b = *(const float2*)(de + (size_t)row * 512 + 2 * t);
    *(__half2*)(hC + (size_t)row * 1024 + 512 + 2 * t) = __floats2half2_rn(a.x, a.y);
    *(__half2*)(hC + (size_t)(Bn + row) * 1024 + 512 + 2 * t) = __floats2half2_rn(b.x, b.y);
}

__device__ __forceinline__ float sigf(float x) { return 1.0f / (1.0f + expf(-x)); }

__global__ void gru_scatter(const float* __restrict__ gi, const float* __restrict__ gh,
                            const float* __restrict__ mem, const int* __restrict__ ids,
                            __half* __restrict__ ch, float* __restrict__ out_mem) {
    int row = blockIdx.x, j = threadIdx.x * 4, id = ids[row];
    size_t b3 = (size_t)row * 1536;
    float4 ir = *(const float4*)(gi + b3 + j);
    float4 hr = *(const float4*)(gh + b3 + j);
    float4 iz = *(const float4*)(gi + b3 + 512 + j);
    float4 hz = *(const float4*)(gh + b3 + 512 + j);
    float4 in4 = *(const float4*)(gi + b3 + 1024 + j);
    float4 hn = *(const float4*)(gh + b3 + 1024 + j);
    float4 hv = *(const float4*)(mem + (size_t)id * 512 + j);
    float4 u;
    { float r = sigf(ir.x + hr.x), z = sigf(iz.x + hz.x);
      float n = tanhf(in4.x + r * hn.x); u.x = (1.f - z) * n + z * hv.x; }
    { float r = sigf(ir.y + hr.y), z = sigf(iz.y + hz.y);
      float n = tanhf(in4.y + r * hn.y); u.y = (1.f - z) * n + z * hv.y; }
    { float r = sigf(ir.z + hr.z), z = sigf(iz.z + hz.z);
      float n = tanhf(in4.z + r * hn.z); u.z = (1.f - z) * n + z * hv.z; }
    { float r = sigf(ir.w + hr.w), z = sigf(iz.w + hz.w);
      float n = tanhf(in4.w + r * hn.w); u.w = (1.f - z) * n + z * hv.w; }
    *(float4*)(out_mem + (size_t)id * 512 + j) = u;
    size_t cb = (size_t)row * 1024 + j;
    *(__half2*)(ch + cb) = __floats2half2_rn(u.x, u.y);
    *(__half2*)(ch + cb + 2) = __floats2half2_rn(u.z, u.w);
}

// ---------- launch ----------
extern "C" void kernel_launch(void* const* d_in, const int* in_sizes, int n_in,
                              void* d_out, int out_size) {
    const float* src_emb  = (const float*)d_in[0];
    const float* dst_emb  = (const float*)d_in[1];
    const float* edge     = (const float*)d_in[2];
    const float* ts       = (const float*)d_in[3];
    const float* memory   = (const float*)d_in[4];
    const float* time_w   = (const float*)d_in[5];
    const float* time_b   = (const float*)d_in[6];
    const float* msg_w1   = (const float*)d_in[7];
    const float* msg_b1   = (const float*)d_in[8];
    const float* msg_w2   = (const float*)d_in[9];
    const float* msg_b2   = (const float*)d_in[10];
    const float* gru_w_ih = (const float*)d_in[11];
    const float* gru_w_hh = (const float*)d_in[12];
    const float* gru_b_ih = (const float*)d_in[13];
    const float* gru_b_hh = (const float*)d_in[14];
    const float* out_w    = (const float*)d_in[15];
    const float* out_b    = (const float*)d_in[16];
    const int*   src_ids  = (const int*)d_in[17];
    const int*   dst_ids  = (const int*)d_in[18];

    float* out_y = (float*)d_out;
    float* out_mem = out_y + (size_t)2 * Bn * 512;

    cudaFuncSetAttribute(hgemm, cudaFuncAttributeMaxDynamicSharedMemorySize, GSMEM);

#define SH(p, g) __half* p; cudaGetSymbolAddress((void**)&p, g)
#define SF(p, g) float* p; cudaGetSymbolAddress((void**)&p, g)
    SH(pXa, hX1a); SH(pMem, hMem); SH(pH1, hH1); SH(pM, hM); SH(pC, hC);
    SH(pW1s, hW1s); SH(pW2, hW2); SH(pWih, hWih); SH(pWhh, hWhh); SH(pWo, hWo);
    SF(pGh, fGh); SF(pGi, fGi); SF(pB1, dB1);
#undef SH
#undef SF

    cudaMemcpyAsync(out_mem, memory, (size_t)Nn * 512 * sizeof(float),
                    cudaMemcpyDeviceToDevice, 0);

    #define CVT(src, dst, n) conv_h<<<((n) / 2 + 255) / 256, 256>>>(src, dst, n)

    w1_pack<<<(1024 * K1 + 255) / 256, 256>>>(msg_w1);
    b1_pack<<<4, 256>>>(msg_b1);
    gather_pack<<<Bn, 256>>>(memory, edge, ts, time_w, time_b, src_ids, dst_ids);
    CVT(gru_w_hh, pWhh, 1536 * 512);

    // layer1 fused: [H1a|H1b] <- X1a @ [W1;W1p]^T, relu, row-split output
    hgemm<<<dim3(8, Bn / 128), 128, GSMEM>>>(pXa, K1, pW1s, K1, K1, pB1,
                                             (float*)0, 0, pH1, 512, 3);
    // gh: [gh_s; gh_d] <- [src_mem; dst_mem] @ Whh^T
    hgemm<<<dim3(12, 2 * Bn / 128), 128, GSMEM>>>(pMem, 512, pWhh, 512, 512,
                                                  gru_b_hh, pGh, 1536, (__half*)0, 0, 0);
    CVT(msg_w2, pW2, 512 * 512);
    // msg2: [Ms; Md] <- [H1a; H1b] @ W2^T
    hgemm<<<dim3(4, 2 * Bn / 128), 128, GSMEM>>>(pH1, 512, pW2, 512, 512,
                                                 msg_b2, (float*)0, 0, pM, 512, 2);
    CVT(gru_w_ih, pWih, 1536 * 512);
    // gi: rows 0:Bn = Ms@Wih (gi_dst), Bn:2Bn = Md@Wih (gi_src)
    hgemm<<<dim3(12, 2 * Bn / 128), 128, GSMEM>>>(pM, 512, pWih, 512, 512,
                                                  gru_b_ih, pGi, 1536, (__half*)0, 0, 0);
    emb_pack<<<Bn, 256>>>(src_emb, dst_emb);
    // src: gi = fGi rows Bn: (from Md), gh = fGh rows 0:
    gru_scatter<<<Bn, 128>>>(pGi + (size_t)Bn * 1536, pGh, memory, src_ids,
                             pC, out_mem);
    // dst: gi = fGi rows 0: (from Ms), gh = fGh rows Bn:
    gru_scatter<<<Bn, 128>>>(pGi, pGh + (size_t)Bn * 1536, memory, dst_ids,
                             pC + (size_t)Bn * 1024, out_mem);
    CVT(out_w, pWo, 512 * 1024);
    // output projection: [2Bn,512] directly into d_out
    hgemm<<<dim3(4, 2 * Bn / 128), 128, GSMEM>>>(pC, 1024, pWo, 1024, 1024,
                                                 out_b, out_y, 512, (__half*)0, 0, 0);
}